// round 3
// baseline (speedup 1.0000x reference)
#include <cuda_runtime.h>

#define Bb 8
#define Nn 256
#define Ff 128
#define Hh 128
#define Oo 64
#define Rr 4   // rows per block

__global__ __launch_bounds__(128) void weaktie_fused_r4(
    const float* __restrict__ local_x,   // [B,N,F]
    const float* __restrict__ global_x,  // [B,N,F]
    const float* __restrict__ mask,      // [B,N,N]
    const int*   __restrict__ key_idx,   // [B]
    const float* __restrict__ hidden,    // [B,N,H]
    const float* __restrict__ fc_w,      // [H, 3F]
    const float* __restrict__ fc_b,      // [H]
    const float* __restrict__ ln_g,      // [H]
    const float* __restrict__ ln_b,      // [H]
    const float* __restrict__ w_ih,      // [3H, H]
    const float* __restrict__ w_hh,      // [3H, H]
    const float* __restrict__ b_ih,      // [3H]
    const float* __restrict__ b_hh,      // [3H]
    const float* __restrict__ out_w,     // [O, H]
    const float* __restrict__ out_b,     // [O]
    float* __restrict__ out,             // [B,N,O]
    float* __restrict__ h_new_out)       // [B,N,H]
{
    __shared__ __align__(16) float mask_s[Rr][Nn];
    __shared__ __align__(16) float comb_s[Rr][3 * Ff];
    __shared__ __align__(16) float x_s[Rr][Hh];
    __shared__ __align__(16) float hf_s[Rr][Hh];
    __shared__ __align__(16) float hn_s[Rr][Hh];
    __shared__ float red_a[4][Rr];
    __shared__ float red_b[4][Rr];

    const int bi = blockIdx.x;           // 0..511
    const int b  = bi >> 6;              // batch
    const int i0 = (bi & 63) << 2;       // first of 4 rows
    const int t  = threadIdx.x;          // 0..127
    const int lane = t & 31;
    const int w    = t >> 5;

    // ---- load mask rows, compute denominators ----
    float v[Rr];
    #pragma unroll
    for (int r = 0; r < Rr; r++) {
        const float* mrow = mask + ((long)b * Nn + (i0 + r)) * Nn;
        float m0 = mrow[t], m1 = mrow[t + 128];
        mask_s[r][t]       = m0;
        mask_s[r][t + 128] = m1;
        v[r] = m0 + m1;
    }
    #pragma unroll
    for (int r = 0; r < Rr; r++) {
        #pragma unroll
        for (int o = 16; o; o >>= 1) v[r] += __shfl_xor_sync(0xffffffffu, v[r], o);
        if (lane == 0) red_a[w][r] = v[r];
    }
    __syncthreads();
    float inv_den[Rr];
    #pragma unroll
    for (int r = 0; r < Rr; r++)
        inv_den[r] = 1.0f / (red_a[0][r] + red_a[1][r] + red_a[2][r] + red_a[3][r] + 1e-6f);

    // ---- weak[r][t] = sum_j mask[r][j] * gx[j][t] / denom[r] ----
    const float* gx = global_x + (long)b * Nn * Ff;
    float acc[Rr] = {0.f, 0.f, 0.f, 0.f};
    #pragma unroll 4
    for (int j = 0; j < Nn; j += 4) {
        float g0 = gx[(j + 0) * Ff + t];
        float g1 = gx[(j + 1) * Ff + t];
        float g2 = gx[(j + 2) * Ff + t];
        float g3 = gx[(j + 3) * Ff + t];
        #pragma unroll
        for (int r = 0; r < Rr; r++) {
            float4 mv = *reinterpret_cast<const float4*>(&mask_s[r][j]);
            acc[r] = fmaf(mv.x, g0, acc[r]);
            acc[r] = fmaf(mv.y, g1, acc[r]);
            acc[r] = fmaf(mv.z, g2, acc[r]);
            acc[r] = fmaf(mv.w, g3, acc[r]);
        }
    }
    const int ki = key_idx[b];
    const float keyf = gx[ki * Ff + t];
    #pragma unroll
    for (int r = 0; r < Rr; r++) {
        comb_s[r][t]          = local_x[((long)b * Nn + (i0 + r)) * Ff + t];
        comb_s[r][Ff + t]     = acc[r] * inv_den[r];
        comb_s[r][2 * Ff + t] = keyf;
    }
    __syncthreads();

    // ---- FC: h[r][t] = comb[r] . fc_w[t,:] + fc_b[t] ----
    const float bias = fc_b[t];
    float hv[Rr] = {bias, bias, bias, bias};
    {
        const float4* w4 = reinterpret_cast<const float4*>(fc_w + t * (3 * Ff));
        #pragma unroll 4
        for (int k = 0; k < (3 * Ff) / 4; k++) {
            float4 wv = w4[k];
            #pragma unroll
            for (int r = 0; r < Rr; r++) {
                float4 cv = reinterpret_cast<const float4*>(comb_s[r])[k];
                hv[r] = fmaf(wv.x, cv.x, hv[r]);
                hv[r] = fmaf(wv.y, cv.y, hv[r]);
                hv[r] = fmaf(wv.z, cv.z, hv[r]);
                hv[r] = fmaf(wv.w, cv.w, hv[r]);
            }
        }
    }

    // ---- LayerNorm over H=128 per row ----
    {
        float sv[Rr];
        #pragma unroll
        for (int r = 0; r < Rr; r++) {
            sv[r] = hv[r];
            #pragma unroll
            for (int o = 16; o; o >>= 1) sv[r] += __shfl_xor_sync(0xffffffffu, sv[r], o);
            if (lane == 0) red_b[w][r] = sv[r];
        }
        __syncthreads();
        float mu[Rr], dv[Rr];
        #pragma unroll
        for (int r = 0; r < Rr; r++) {
            mu[r] = (red_b[0][r] + red_b[1][r] + red_b[2][r] + red_b[3][r]) * (1.0f / Hh);
            dv[r] = hv[r] - mu[r];
        }
        float sq[Rr];
        #pragma unroll
        for (int r = 0; r < Rr; r++) {
            sq[r] = dv[r] * dv[r];
            #pragma unroll
            for (int o = 16; o; o >>= 1) sq[r] += __shfl_xor_sync(0xffffffffu, sq[r], o);
            if (lane == 0) red_a[w][r] = sq[r];
        }
        __syncthreads();
        const float g = ln_g[t], be = ln_b[t];
        #pragma unroll
        for (int r = 0; r < Rr; r++) {
            float var = (red_a[0][r] + red_a[1][r] + red_a[2][r] + red_a[3][r]) * (1.0f / Hh);
            float xn  = dv[r] * rsqrtf(var + 1e-5f) * g + be;
            x_s[r][t] = fmaxf(xn, 0.f);
            hf_s[r][t] = hidden[((long)b * Nn + (i0 + r)) * Hh + t];
        }
    }
    __syncthreads();

    // ---- GRU pass 1: input gates (w_ih . x) ----
    float gir[Rr], giz[Rr], gin[Rr];
    {
        const float bir = b_ih[t], biz = b_ih[Hh + t], bin_ = b_ih[2 * Hh + t];
        #pragma unroll
        for (int r = 0; r < Rr; r++) { gir[r] = bir; giz[r] = biz; gin[r] = bin_; }
        const float4* wr4 = reinterpret_cast<const float4*>(w_ih + t * Hh);
        const float4* wz4 = reinterpret_cast<const float4*>(w_ih + (Hh + t) * Hh);
        const float4* wn4 = reinterpret_cast<const float4*>(w_ih + (2 * Hh + t) * Hh);
        #pragma unroll 2
        for (int k = 0; k < Hh / 4; k++) {
            float4 ar = wr4[k], az = wz4[k], an = wn4[k];
            #pragma unroll
            for (int r = 0; r < Rr; r++) {
                float4 xv = reinterpret_cast<const float4*>(x_s[r])[k];
                gir[r] = fmaf(ar.x,xv.x,fmaf(ar.y,xv.y,fmaf(ar.z,xv.z,fmaf(ar.w,xv.w,gir[r]))));
                giz[r] = fmaf(az.x,xv.x,fmaf(az.y,xv.y,fmaf(az.z,xv.z,fmaf(az.w,xv.w,giz[r]))));
                gin[r] = fmaf(an.x,xv.x,fmaf(an.y,xv.y,fmaf(an.z,xv.z,fmaf(an.w,xv.w,gin[r]))));
            }
        }
    }
    // ---- GRU pass 2: hidden gates (w_hh . hf) ----
    float ghr[Rr], ghz[Rr], ghn[Rr];
    {
        const float br = b_hh[t], bz = b_hh[Hh + t], bn = b_hh[2 * Hh + t];
        #pragma unroll
        for (int r = 0; r < Rr; r++) { ghr[r] = br; ghz[r] = bz; ghn[r] = bn; }
        const float4* wr4 = reinterpret_cast<const float4*>(w_hh + t * Hh);
        const float4* wz4 = reinterpret_cast<const float4*>(w_hh + (Hh + t) * Hh);
        const float4* wn4 = reinterpret_cast<const float4*>(w_hh + (2 * Hh + t) * Hh);
        #pragma unroll 2
        for (int k = 0; k < Hh / 4; k++) {
            float4 ar = wr4[k], az = wz4[k], an = wn4[k];
            #pragma unroll
            for (int r = 0; r < Rr; r++) {
                float4 hx = reinterpret_cast<const float4*>(hf_s[r])[k];
                ghr[r] = fmaf(ar.x,hx.x,fmaf(ar.y,hx.y,fmaf(ar.z,hx.z,fmaf(ar.w,hx.w,ghr[r]))));
                ghz[r] = fmaf(az.x,hx.x,fmaf(az.y,hx.y,fmaf(az.z,hx.z,fmaf(az.w,hx.w,ghz[r]))));
                ghn[r] = fmaf(an.x,hx.x,fmaf(an.y,hx.y,fmaf(an.z,hx.z,fmaf(an.w,hx.w,ghn[r]))));
            }
        }
    }
    // ---- gates + h_new ----
    #pragma unroll
    for (int r = 0; r < Rr; r++) {
        float rg = 1.f / (1.f + __expf(-(gir[r] + ghr[r])));
        float zg = 1.f / (1.f + __expf(-(giz[r] + ghz[r])));
        float ng = tanhf(gin[r] + rg * ghn[r]);
        float hn = (1.f - zg) * ng + zg * hf_s[r][t];
        hn_s[r][t] = hn;
        h_new_out[((long)b * Nn + (i0 + r)) * Hh + t] = hn;
    }
    __syncthreads();

    // ---- out projection: 128 threads = 64 outputs x 2 row-pairs ----
    {
        const int o  = t & 63;
        const int r0 = (t >> 6) * 2;          // rows r0, r0+1
        const float ob = out_b[o];
        float a0 = ob, a1 = ob;
        const float4* ow = reinterpret_cast<const float4*>(out_w + o * Hh);
        #pragma unroll 4
        for (int k = 0; k < Hh / 4; k++) {
            float4 wv = ow[k];
            float4 h0 = reinterpret_cast<const float4*>(hn_s[r0])[k];
            float4 h1 = reinterpret_cast<const float4*>(hn_s[r0 + 1])[k];
            a0 = fmaf(wv.x,h0.x,fmaf(wv.y,h0.y,fmaf(wv.z,h0.z,fmaf(wv.w,h0.w,a0))));
            a1 = fmaf(wv.x,h1.x,fmaf(wv.y,h1.y,fmaf(wv.z,h1.z,fmaf(wv.w,h1.w,a1))));
        }
        out[((long)b * Nn + (i0 + r0)) * Oo + o]     = a0;
        out[((long)b * Nn + (i0 + r0 + 1)) * Oo + o] = a1;
    }
}

extern "C" void kernel_launch(void* const* d_in, const int* in_sizes, int n_in,
                              void* d_out, int out_size) {
    const float* local_x  = (const float*)d_in[0];
    const float* global_x = (const float*)d_in[1];
    const float* mask     = (const float*)d_in[2];
    const int*   key_idx  = (const int*)  d_in[3];
    const float* hidden   = (const float*)d_in[4];
    const float* fc_w     = (const float*)d_in[5];
    const float* fc_b     = (const float*)d_in[6];
    const float* ln_g     = (const float*)d_in[7];
    const float* ln_b     = (const float*)d_in[8];
    const float* w_ih     = (const float*)d_in[9];
    const float* w_hh     = (const float*)d_in[10];
    const float* b_ih     = (const float*)d_in[11];
    const float* b_hh     = (const float*)d_in[12];
    const float* out_w    = (const float*)d_in[13];
    const float* out_b    = (const float*)d_in[14];

    float* out       = (float*)d_out;                  // [B,N,O]
    float* h_new_out = (float*)d_out + Bb * Nn * Oo;   // [B,N,H]

    weaktie_fused_r4<<<(Bb * Nn) / Rr, 128>>>(local_x, global_x, mask, key_idx, hidden,
                                              fc_w, fc_b, ln_g, ln_b, w_ih, w_hh,
                                              b_ih, b_hh, out_w, out_b, out, h_new_out);
}

// round 5
// speedup vs baseline: 2.1889x; 2.1889x over previous
#include <cuda_runtime.h>

#define Bb 8
#define Nn 256
#define Ff 128
#define Hh 128
#define Oo 64
#define Rr 4   // rows per block

// Transposed weight scratch: [k4][unit][4] quad-interleaved, so that a warp of
// consecutive units reads 512B contiguous per k4 (coalesced, 4 wavefronts).
__device__ float4 fc_wT4 [Hh * (3 * Ff) / 4];   // 12288 quads
__device__ float4 w_ihT4 [(3 * Hh) * Hh / 4];   // 12288
__device__ float4 w_hhT4 [(3 * Hh) * Hh / 4];   // 12288
__device__ float4 out_wT4[Oo * Hh / 4];         // 2048

__global__ void transpose_weights(const float* __restrict__ fc_w,
                                  const float* __restrict__ w_ih,
                                  const float* __restrict__ w_hh,
                                  const float* __restrict__ out_w)
{
    const int tid    = blockIdx.x * blockDim.x + threadIdx.x;
    const int stride = gridDim.x * blockDim.x;

    // fc_w: [128 u][384 k] -> fc_wT4[k4*128 + u]
    for (int q = tid; q < Hh * (3 * Ff / 4); q += stride) {
        int u  = q / (3 * Ff / 4);
        int k4 = q % (3 * Ff / 4);
        fc_wT4[k4 * Hh + u] = reinterpret_cast<const float4*>(fc_w)[u * (3 * Ff / 4) + k4];
    }
    // w_ih / w_hh: [384 r][128 k] -> T4[k4*384 + r]
    for (int q = tid; q < (3 * Hh) * (Hh / 4); q += stride) {
        int r  = q / (Hh / 4);
        int k4 = q % (Hh / 4);
        w_ihT4[k4 * (3 * Hh) + r] = reinterpret_cast<const float4*>(w_ih)[r * (Hh / 4) + k4];
        w_hhT4[k4 * (3 * Hh) + r] = reinterpret_cast<const float4*>(w_hh)[r * (Hh / 4) + k4];
    }
    // out_w: [64 o][128 k] -> T4[k4*64 + o]
    for (int q = tid; q < Oo * (Hh / 4); q += stride) {
        int o  = q / (Hh / 4);
        int k4 = q % (Hh / 4);
        out_wT4[k4 * Oo + o] = reinterpret_cast<const float4*>(out_w)[o * (Hh / 4) + k4];
    }
}

__global__ __launch_bounds__(128) void weaktie_fused_r4t(
    const float* __restrict__ local_x,   // [B,N,F]
    const float* __restrict__ global_x,  // [B,N,F]
    const float* __restrict__ mask,      // [B,N,N]
    const int*   __restrict__ key_idx,   // [B]
    const float* __restrict__ hidden,    // [B,N,H]
    const float* __restrict__ fc_b,      // [H]
    const float* __restrict__ ln_g,      // [H]
    const float* __restrict__ ln_b,      // [H]
    const float* __restrict__ b_ih,      // [3H]
    const float* __restrict__ b_hh,      // [3H]
    const float* __restrict__ out_b,     // [O]
    float* __restrict__ out,             // [B,N,O]
    float* __restrict__ h_new_out)       // [B,N,H]
{
    __shared__ __align__(16) float mask_s[Rr][Nn];
    __shared__ __align__(16) float comb_s[Rr][3 * Ff];
    __shared__ __align__(16) float x_s[Rr][Hh];
    __shared__ __align__(16) float hf_s[Rr][Hh];
    __shared__ __align__(16) float hn_s[Rr][Hh];
    __shared__ float red_a[4][Rr];
    __shared__ float red_b[4][Rr];

    const int bi = blockIdx.x;           // 0..511
    const int b  = bi >> 6;              // batch
    const int i0 = (bi & 63) << 2;       // first of 4 rows
    const int t  = threadIdx.x;          // 0..127
    const int lane = t & 31;
    const int w    = t >> 5;

    // ---- load mask rows, compute denominators ----
    float v[Rr];
    #pragma unroll
    for (int r = 0; r < Rr; r++) {
        const float* mrow = mask + ((long)b * Nn + (i0 + r)) * Nn;
        float m0 = mrow[t], m1 = mrow[t + 128];
        mask_s[r][t]       = m0;
        mask_s[r][t + 128] = m1;
        v[r] = m0 + m1;
    }
    #pragma unroll
    for (int r = 0; r < Rr; r++) {
        #pragma unroll
        for (int o = 16; o; o >>= 1) v[r] += __shfl_xor_sync(0xffffffffu, v[r], o);
        if (lane == 0) red_a[w][r] = v[r];
    }
    __syncthreads();
    float inv_den[Rr];
    #pragma unroll
    for (int r = 0; r < Rr; r++)
        inv_den[r] = 1.0f / (red_a[0][r] + red_a[1][r] + red_a[2][r] + red_a[3][r] + 1e-6f);

    // ---- weak[r][t] = sum_j mask[r][j] * gx[j][t] / denom[r] ----
    const float* gx = global_x + (long)b * Nn * Ff;
    float acc[Rr] = {0.f, 0.f, 0.f, 0.f};
    #pragma unroll 4
    for (int j = 0; j < Nn; j += 4) {
        float g0 = gx[(j + 0) * Ff + t];
        float g1 = gx[(j + 1) * Ff + t];
        float g2 = gx[(j + 2) * Ff + t];
        float g3 = gx[(j + 3) * Ff + t];
        #pragma unroll
        for (int r = 0; r < Rr; r++) {
            float4 mv = *reinterpret_cast<const float4*>(&mask_s[r][j]);
            acc[r] = fmaf(mv.x, g0, acc[r]);
            acc[r] = fmaf(mv.y, g1, acc[r]);
            acc[r] = fmaf(mv.z, g2, acc[r]);
            acc[r] = fmaf(mv.w, g3, acc[r]);
        }
    }
    const int ki = key_idx[b];
    const float keyf = gx[ki * Ff + t];
    #pragma unroll
    for (int r = 0; r < Rr; r++) {
        comb_s[r][t]          = local_x[((long)b * Nn + (i0 + r)) * Ff + t];
        comb_s[r][Ff + t]     = acc[r] * inv_den[r];
        comb_s[r][2 * Ff + t] = keyf;
    }
    __syncthreads();

    // ---- FC: h[r][t] = comb[r] . fc_w[t,:] + fc_b[t]  (coalesced transposed reads) ----
    const float bias = fc_b[t];
    float hv[Rr] = {bias, bias, bias, bias};
    {
        #pragma unroll 8
        for (int k = 0; k < (3 * Ff) / 4; k++) {
            float4 wv = fc_wT4[k * Hh + t];
            #pragma unroll
            for (int r = 0; r < Rr; r++) {
                float4 cv = reinterpret_cast<const float4*>(comb_s[r])[k];
                hv[r] = fmaf(wv.x, cv.x, hv[r]);
                hv[r] = fmaf(wv.y, cv.y, hv[r]);
                hv[r] = fmaf(wv.z, cv.z, hv[r]);
                hv[r] = fmaf(wv.w, cv.w, hv[r]);
            }
        }
    }

    // ---- LayerNorm over H=128 per row ----
    {
        float sv[Rr];
        #pragma unroll
        for (int r = 0; r < Rr; r++) {
            sv[r] = hv[r];
            #pragma unroll
            for (int o = 16; o; o >>= 1) sv[r] += __shfl_xor_sync(0xffffffffu, sv[r], o);
            if (lane == 0) red_b[w][r] = sv[r];
        }
        __syncthreads();
        float mu[Rr], dv[Rr];
        #pragma unroll
        for (int r = 0; r < Rr; r++) {
            mu[r] = (red_b[0][r] + red_b[1][r] + red_b[2][r] + red_b[3][r]) * (1.0f / Hh);
            dv[r] = hv[r] - mu[r];
        }
        float sq[Rr];
        #pragma unroll
        for (int r = 0; r < Rr; r++) {
            sq[r] = dv[r] * dv[r];
            #pragma unroll
            for (int o = 16; o; o >>= 1) sq[r] += __shfl_xor_sync(0xffffffffu, sq[r], o);
            if (lane == 0) red_a[w][r] = sq[r];
        }
        __syncthreads();
        const float g = ln_g[t], be = ln_b[t];
        #pragma unroll
        for (int r = 0; r < Rr; r++) {
            float var = (red_a[0][r] + red_a[1][r] + red_a[2][r] + red_a[3][r]) * (1.0f / Hh);
            float xn  = dv[r] * rsqrtf(var + 1e-5f) * g + be;
            x_s[r][t] = fmaxf(xn, 0.f);
            hf_s[r][t] = hidden[((long)b * Nn + (i0 + r)) * Hh + t];
        }
    }
    __syncthreads();

    // ---- GRU pass 1: input gates (w_ih . x), coalesced transposed reads ----
    float gir[Rr], giz[Rr], gin[Rr];
    {
        const float bir = b_ih[t], biz = b_ih[Hh + t], bin_ = b_ih[2 * Hh + t];
        #pragma unroll
        for (int r = 0; r < Rr; r++) { gir[r] = bir; giz[r] = biz; gin[r] = bin_; }
        #pragma unroll 4
        for (int k = 0; k < Hh / 4; k++) {
            float4 ar = w_ihT4[k * (3 * Hh) + t];
            float4 az = w_ihT4[k * (3 * Hh) + Hh + t];
            float4 an = w_ihT4[k * (3 * Hh) + 2 * Hh + t];
            #pragma unroll
            for (int r = 0; r < Rr; r++) {
                float4 xv = reinterpret_cast<const float4*>(x_s[r])[k];
                gir[r] = fmaf(ar.x,xv.x,fmaf(ar.y,xv.y,fmaf(ar.z,xv.z,fmaf(ar.w,xv.w,gir[r]))));
                giz[r] = fmaf(az.x,xv.x,fmaf(az.y,xv.y,fmaf(az.z,xv.z,fmaf(az.w,xv.w,giz[r]))));
                gin[r] = fmaf(an.x,xv.x,fmaf(an.y,xv.y,fmaf(an.z,xv.z,fmaf(an.w,xv.w,gin[r]))));
            }
        }
    }
    // ---- GRU pass 2: hidden gates (w_hh . hf) ----
    float ghr[Rr], ghz[Rr], ghn[Rr];
    {
        const float br = b_hh[t], bz = b_hh[Hh + t], bn = b_hh[2 * Hh + t];
        #pragma unroll
        for (int r = 0; r < Rr; r++) { ghr[r] = br; ghz[r] = bz; ghn[r] = bn; }
        #pragma unroll 4
        for (int k = 0; k < Hh / 4; k++) {
            float4 ar = w_hhT4[k * (3 * Hh) + t];
            float4 az = w_hhT4[k * (3 * Hh) + Hh + t];
            float4 an = w_hhT4[k * (3 * Hh) + 2 * Hh + t];
            #pragma unroll
            for (int r = 0; r < Rr; r++) {
                float4 hx = reinterpret_cast<const float4*>(hf_s[r])[k];
                ghr[r] = fmaf(ar.x,hx.x,fmaf(ar.y,hx.y,fmaf(ar.z,hx.z,fmaf(ar.w,hx.w,ghr[r]))));
                ghz[r] = fmaf(az.x,hx.x,fmaf(az.y,hx.y,fmaf(az.z,hx.z,fmaf(az.w,hx.w,ghz[r]))));
                ghn[r] = fmaf(an.x,hx.x,fmaf(an.y,hx.y,fmaf(an.z,hx.z,fmaf(an.w,hx.w,ghn[r]))));
            }
        }
    }
    // ---- gates + h_new ----
    #pragma unroll
    for (int r = 0; r < Rr; r++) {
        float rg = 1.f / (1.f + __expf(-(gir[r] + ghr[r])));
        float zg = 1.f / (1.f + __expf(-(giz[r] + ghz[r])));
        float ng = tanhf(gin[r] + rg * ghn[r]);
        float hn = (1.f - zg) * ng + zg * hf_s[r][t];
        hn_s[r][t] = hn;
        h_new_out[((long)b * Nn + (i0 + r)) * Hh + t] = hn;
    }
    __syncthreads();

    // ---- out projection: 128 threads = 64 outputs x 2 row-pairs ----
    {
        const int o  = t & 63;
        const int r0 = (t >> 6) * 2;          // rows r0, r0+1
        const float ob = out_b[o];
        float a0 = ob, a1 = ob;
        #pragma unroll 4
        for (int k = 0; k < Hh / 4; k++) {
            float4 wv = out_wT4[k * Oo + o];
            float4 h0 = reinterpret_cast<const float4*>(hn_s[r0])[k];
            float4 h1 = reinterpret_cast<const float4*>(hn_s[r0 + 1])[k];
            a0 = fmaf(wv.x,h0.x,fmaf(wv.y,h0.y,fmaf(wv.z,h0.z,fmaf(wv.w,h0.w,a0))));
            a1 = fmaf(wv.x,h1.x,fmaf(wv.y,h1.y,fmaf(wv.z,h1.z,fmaf(wv.w,h1.w,a1))));
        }
        out[((long)b * Nn + (i0 + r0)) * Oo + o]     = a0;
        out[((long)b * Nn + (i0 + r0 + 1)) * Oo + o] = a1;
    }
}

extern "C" void kernel_launch(void* const* d_in, const int* in_sizes, int n_in,
                              void* d_out, int out_size) {
    const float* local_x  = (const float*)d_in[0];
    const float* global_x = (const float*)d_in[1];
    const float* mask     = (const float*)d_in[2];
    const int*   key_idx  = (const int*)  d_in[3];
    const float* hidden   = (const float*)d_in[4];
    const float* fc_w     = (const float*)d_in[5];
    const float* fc_b     = (const float*)d_in[6];
    const float* ln_g     = (const float*)d_in[7];
    const float* ln_b     = (const float*)d_in[8];
    const float* w_ih     = (const float*)d_in[9];
    const float* w_hh     = (const float*)d_in[10];
    const float* b_ih     = (const float*)d_in[11];
    const float* b_hh     = (const float*)d_in[12];
    const float* out_w    = (const float*)d_in[13];
    const float* out_b    = (const float*)d_in[14];

    float* out       = (float*)d_out;                  // [B,N,O]
    float* h_new_out = (float*)d_out + Bb * Nn * Oo;   // [B,N,H]

    transpose_weights<<<64, 256>>>(fc_w, w_ih, w_hh, out_w);
    weaktie_fused_r4t<<<(Bb * Nn) / Rr, 128>>>(local_x, global_x, mask, key_idx, hidden,
                                               fc_b, ln_g, ln_b,
                                               b_ih, b_hh, out_b, out, h_new_out);
}

// round 8
// speedup vs baseline: 2.3474x; 1.0724x over previous
#include <cuda_runtime.h>

#define Bb 8
#define Nn 256
#define Ff 128
#define Hh 128
#define Oo 64
#define Rr 4   // rows per block

// Transposed weight scratch: [k4][unit] quad-interleaved -> warp-coalesced reads.
__device__ float4 fc_wT4 [Hh * (3 * Ff) / 4];   // 12288 quads
__device__ float4 w_ihT4 [(3 * Hh) * Hh / 4];   // 12288
__device__ float4 w_hhT4 [(3 * Hh) * Hh / 4];   // 12288
__device__ float4 out_wT4[Oo * Hh / 4];         // 2048

__global__ void transpose_weights(const float* __restrict__ fc_w,
                                  const float* __restrict__ w_ih,
                                  const float* __restrict__ w_hh,
                                  const float* __restrict__ out_w)
{
    const int tid    = blockIdx.x * blockDim.x + threadIdx.x;
    const int stride = gridDim.x * blockDim.x;

    for (int q = tid; q < Hh * (3 * Ff / 4); q += stride) {
        int u  = q / (3 * Ff / 4);
        int k4 = q % (3 * Ff / 4);
        fc_wT4[k4 * Hh + u] = reinterpret_cast<const float4*>(fc_w)[u * (3 * Ff / 4) + k4];
    }
    for (int q = tid; q < (3 * Hh) * (Hh / 4); q += stride) {
        int r  = q / (Hh / 4);
        int k4 = q % (Hh / 4);
        w_ihT4[k4 * (3 * Hh) + r] = reinterpret_cast<const float4*>(w_ih)[r * (Hh / 4) + k4];
        w_hhT4[k4 * (3 * Hh) + r] = reinterpret_cast<const float4*>(w_hh)[r * (Hh / 4) + k4];
    }
    for (int q = tid; q < Oo * (Hh / 4); q += stride) {
        int o  = q / (Hh / 4);
        int k4 = q % (Hh / 4);
        out_wT4[k4 * Oo + o] = reinterpret_cast<const float4*>(out_w)[o * (Hh / 4) + k4];
    }
}

__global__ __launch_bounds__(256, 4) void weaktie_fused_r4s(
    const float* __restrict__ local_x,   // [B,N,F]
    const float* __restrict__ global_x,  // [B,N,F]
    const float* __restrict__ mask,      // [B,N,N]
    const int*   __restrict__ key_idx,   // [B]
    const float* __restrict__ hidden,    // [B,N,H]
    const float* __restrict__ fc_b,      // [H]
    const float* __restrict__ ln_g,      // [H]
    const float* __restrict__ ln_b,      // [H]
    const float* __restrict__ b_ih,      // [3H]
    const float* __restrict__ b_hh,      // [3H]
    const float* __restrict__ out_b,     // [O]
    float* __restrict__ out,             // [B,N,O]
    float* __restrict__ h_new_out)       // [B,N,H]
{
    __shared__ __align__(16) float mask_s[Rr][Nn];       // 4 KB
    __shared__ __align__(16) float comb_s[Rr][3 * Ff];   // 6 KB
    __shared__ __align__(16) float part_s[2][Rr][Hh];    // 4 KB (weak partials, then FC partials)
    __shared__ __align__(16) float x_s[Rr][Hh];          // 2 KB
    __shared__ __align__(16) float hf_s[Rr][Hh];         // 2 KB
    __shared__ __align__(16) float hn_s[Rr][Hh];         // 2 KB
    __shared__ __align__(16) float gi_s[3][Rr][Hh];      // 6 KB
    __shared__ __align__(16) float gh_s[3][Rr][Hh];      // 6 KB
    __shared__ float red_a[8][Rr];
    __shared__ float red_b[8][Rr];

    const int bi   = blockIdx.x;         // 0..511
    const int b    = bi >> 6;            // batch
    const int i0   = (bi & 63) << 2;     // first of 4 rows
    const int t    = threadIdx.x;        // 0..255
    const int u    = t & 127;            // unit index
    const int half = t >> 7;             // 0/1
    const int lane = t & 31;
    const int w    = t >> 5;             // warp 0..7

    // ---- mask rows (full 256 wide) + denominators ----
    float m[Rr];
    #pragma unroll
    for (int r = 0; r < Rr; r++) {
        m[r] = mask[((long)b * Nn + (i0 + r)) * Nn + t];
        mask_s[r][t] = m[r];
    }
    #pragma unroll
    for (int r = 0; r < Rr; r++) {
        #pragma unroll
        for (int o = 16; o; o >>= 1) m[r] += __shfl_xor_sync(0xffffffffu, m[r], o);
        if (lane == 0) red_a[w][r] = m[r];
    }
    __syncthreads();
    float inv_den[Rr];
    #pragma unroll
    for (int r = 0; r < Rr; r++) {
        float s = red_a[0][r] + red_a[1][r] + red_a[2][r] + red_a[3][r]
                + red_a[4][r] + red_a[5][r] + red_a[6][r] + red_a[7][r];
        inv_den[r] = 1.0f / (s + 1e-6f);
    }

    // ---- weak aggregation: halves split j-range ----
    const float* gx = global_x + (long)b * Nn * Ff;
    {
        float acc[Rr] = {0.f, 0.f, 0.f, 0.f};
        const int j0 = half << 7;        // 0 or 128
        #pragma unroll 4
        for (int j = j0; j < j0 + 128; j += 4) {
            float g0 = gx[(j + 0) * Ff + u];
            float g1 = gx[(j + 1) * Ff + u];
            float g2 = gx[(j + 2) * Ff + u];
            float g3 = gx[(j + 3) * Ff + u];
            #pragma unroll
            for (int r = 0; r < Rr; r++) {
                float4 mv = *reinterpret_cast<const float4*>(&mask_s[r][j]);
                acc[r] = fmaf(mv.x, g0, acc[r]);
                acc[r] = fmaf(mv.y, g1, acc[r]);
                acc[r] = fmaf(mv.z, g2, acc[r]);
                acc[r] = fmaf(mv.w, g3, acc[r]);
            }
        }
        #pragma unroll
        for (int r = 0; r < Rr; r++) part_s[half][r][u] = acc[r];
    }
    const int ki = key_idx[b];
    const float keyf = gx[ki * Ff + u];
    __syncthreads();

    // ---- assemble combined input: halves split rows ----
    {
        const int r0 = half << 1;
        #pragma unroll
        for (int rr = r0; rr < r0 + 2; rr++) {
            comb_s[rr][u]          = local_x[((long)b * Nn + (i0 + rr)) * Ff + u];
            comb_s[rr][Ff + u]     = (part_s[0][rr][u] + part_s[1][rr][u]) * inv_den[rr];
            comb_s[rr][2 * Ff + u] = keyf;
        }
    }
    __syncthreads();

    // ---- FC: halves split k-range (48 quads each) ----
    {
        float hv[Rr] = {0.f, 0.f, 0.f, 0.f};
        const int kbeg = half * 48;
        #pragma unroll 8
        for (int k = kbeg; k < kbeg + 48; k++) {
            float4 wv = fc_wT4[k * Hh + u];
            #pragma unroll
            for (int r = 0; r < Rr; r++) {
                float4 cv = reinterpret_cast<const float4*>(comb_s[r])[k];
                hv[r] = fmaf(wv.x, cv.x, hv[r]);
                hv[r] = fmaf(wv.y, cv.y, hv[r]);
                hv[r] = fmaf(wv.z, cv.z, hv[r]);
                hv[r] = fmaf(wv.w, cv.w, hv[r]);
            }
        }
        __syncthreads();                   // part_s weak-reads done everywhere
        #pragma unroll
        for (int r = 0; r < Rr; r++) part_s[half][r][u] = hv[r];
    }
    __syncthreads();

    // ---- LayerNorm (computed redundantly by both halves) ----
    {
        const float bias = fc_b[u];
        float hh[Rr], sv[Rr];
        #pragma unroll
        for (int r = 0; r < Rr; r++) {
            hh[r] = part_s[0][r][u] + part_s[1][r][u] + bias;
            sv[r] = hh[r];
            #pragma unroll
            for (int o = 16; o; o >>= 1) sv[r] += __shfl_xor_sync(0xffffffffu, sv[r], o);
            if (lane == 0) red_b[w][r] = sv[r];
        }
        __syncthreads();
        float dv[Rr], sq[Rr];
        #pragma unroll
        for (int r = 0; r < Rr; r++) {
            float mu = (red_b[0][r] + red_b[1][r] + red_b[2][r] + red_b[3][r]) * (1.0f / Hh);
            dv[r] = hh[r] - mu;
            sq[r] = dv[r] * dv[r];
            #pragma unroll
            for (int o = 16; o; o >>= 1) sq[r] += __shfl_xor_sync(0xffffffffu, sq[r], o);
            if (lane == 0) red_a[w][r] = sq[r];
        }
        __syncthreads();
        const float g = ln_g[u], be = ln_b[u];
        if (half == 0) {
            #pragma unroll
            for (int r = 0; r < Rr; r++) {
                float var = (red_a[0][r] + red_a[1][r] + red_a[2][r] + red_a[3][r]) * (1.0f / Hh);
                float xn  = dv[r] * rsqrtf(var + 1e-5f) * g + be;
                x_s[r][u] = fmaxf(xn, 0.f);
            }
        }
        // hidden loads: halves split rows
        const int r0 = half << 1;
        #pragma unroll
        for (int rr = r0; rr < r0 + 2; rr++)
            hf_s[rr][u] = hidden[((long)b * Nn + (i0 + rr)) * Hh + u];
    }
    __syncthreads();

    // ---- GRU: half 0 computes input gates (w_ih.x), half 1 hidden gates (w_hh.hf) ----
    {
        const float* bias_v = half ? b_hh : b_ih;
        const float4* W     = half ? w_hhT4 : w_ihT4;
        const float (*A)[Hh] = half ? hf_s : x_s;
        float gr[Rr], gz[Rr], gn[Rr];
        const float br = bias_v[u], bz = bias_v[Hh + u], bn = bias_v[2 * Hh + u];
        #pragma unroll
        for (int r = 0; r < Rr; r++) { gr[r] = br; gz[r] = bz; gn[r] = bn; }
        #pragma unroll 4
        for (int k = 0; k < Hh / 4; k++) {
            float4 ar = W[k * (3 * Hh) + u];
            float4 az = W[k * (3 * Hh) + Hh + u];
            float4 an = W[k * (3 * Hh) + 2 * Hh + u];
            #pragma unroll
            for (int r = 0; r < Rr; r++) {
                float4 av = reinterpret_cast<const float4*>(A[r])[k];
                gr[r] = fmaf(ar.x,av.x,fmaf(ar.y,av.y,fmaf(ar.z,av.z,fmaf(ar.w,av.w,gr[r]))));
                gz[r] = fmaf(az.x,av.x,fmaf(az.y,av.y,fmaf(az.z,av.z,fmaf(az.w,av.w,gz[r]))));
                gn[r] = fmaf(an.x,av.x,fmaf(an.y,av.y,fmaf(an.z,av.z,fmaf(an.w,av.w,gn[r]))));
            }
        }
        float (*G)[Rr][Hh] = half ? gh_s : gi_s;
        #pragma unroll
        for (int r = 0; r < Rr; r++) {
            G[0][r][u] = gr[r];
            G[1][r][u] = gz[r];
            G[2][r][u] = gn[r];
        }
    }
    __syncthreads();

    // ---- gates + h_new: halves split rows ----
    {
        const int r0 = half << 1;
        #pragma unroll
        for (int rr = r0; rr < r0 + 2; rr++) {
            float rg = 1.f / (1.f + __expf(-(gi_s[0][rr][u] + gh_s[0][rr][u])));
            float zg = 1.f / (1.f + __expf(-(gi_s[1][rr][u] + gh_s[1][rr][u])));
            float ng = tanhf(gi_s[2][rr][u] + rg * gh_s[2][rr][u]);
            float hn = (1.f - zg) * ng + zg * hf_s[rr][u];
            hn_s[rr][u] = hn;
            h_new_out[((long)b * Nn + (i0 + rr)) * Hh + u] = hn;
        }
    }
    __syncthreads();

    // ---- out projection: 256 threads = 64 outputs x 4 rows ----
    {
        const int o   = t & 63;
        const int row = t >> 6;              // 0..3
        float a0 = out_b[o];
        #pragma unroll 8
        for (int k = 0; k < Hh / 4; k++) {
            float4 wv = out_wT4[k * Oo + o];
            float4 h0 = reinterpret_cast<const float4*>(hn_s[row])[k];
            a0 = fmaf(wv.x,h0.x,fmaf(wv.y,h0.y,fmaf(wv.z,h0.z,fmaf(wv.w,h0.w,a0))));
        }
        out[((long)b * Nn + (i0 + row)) * Oo + o] = a0;
    }
}

extern "C" void kernel_launch(void* const* d_in, const int* in_sizes, int n_in,
                              void* d_out, int out_size) {
    const float* local_x  = (const float*)d_in[0];
    const float* global_x = (const float*)d_in[1];
    const float* mask     = (const float*)d_in[2];
    const int*   key_idx  = (const int*)  d_in[3];
    const float* hidden   = (const float*)d_in[4];
    const float* fc_w     = (const float*)d_in[5];
    const float* fc_b     = (const float*)d_in[6];
    const float* ln_g     = (const float*)d_in[7];
    const float* ln_b     = (const float*)d_in[8];
    const float* w_ih     = (const float*)d_in[9];
    const float* w_hh     = (const float*)d_in[10];
    const float* b_ih     = (const float*)d_in[11];
    const float* b_hh     = (const float*)d_in[12];
    const float* out_w    = (const float*)d_in[13];
    const float* out_b    = (const float*)d_in[14];

    float* out       = (float*)d_out;                  // [B,N,O]
    float* h_new_out = (float*)d_out + Bb * Nn * Oo;   // [B,N,H]

    transpose_weights<<<148, 256>>>(fc_w, w_ih, w_hh, out_w);
    weaktie_fused_r4s<<<(Bb * Nn) / Rr, 256>>>(local_x, global_x, mask, key_idx, hidden,
                                               fc_b, ln_g, ln_b,
                                               b_ih, b_hh, out_b, out, h_new_out);
}